// round 12
// baseline (speedup 1.0000x reference)
#include <cuda_runtime.h>
#include <cuda_fp16.h>
#include <math.h>
#include <stdint.h>

// Problem constants (fixed by the reference)
#define B_   16
#define NQ_  2048
#define NK_  2048
#define D_   128

// Tiling
#define BM       128     // queries per block
#define BN       64      // keys per tile
#define NT       32      // NK_/BN tiles
#define NTHREADS 256     // 8 warps

// smem pitches — chosen for conflict-free mma fragment loads:
//  word-pitch ≡ 4 (mod 32) -> A/B row-fragment banks 4g+t all distinct
//  word-pitch ≡ 8 (mod 32) -> V pair-fragment banks 8t+g all distinct
#define QPH 136          // Qs pitch in halves (68 words ≡ 4 mod 32)
#define KPH 136          // Ks pitch in halves
#define VPW 136          // Vp pitch in half2 words (136 ≡ 8 mod 32)
#define EPH 72           // Es pitch in halves (36 words ≡ 4 mod 32)

// smem byte layout (all 16B aligned)
#define QS_OFF   0
#define QS_BYTES (BM * QPH * 2)                 // 34816
#define KS_OFF   (QS_OFF + QS_BYTES)
#define KS_BYTES (BN * KPH * 2)                 // 17408 per buffer
#define VP_OFF   (KS_OFF + 2 * KS_BYTES)
#define VP_BYTES ((BN/2) * VPW * 4)             // 17408 per buffer
#define ES_OFF   (VP_OFF + 2 * VP_BYTES)
#define ES_BYTES (BM * EPH * 2)                 // 18432
#define LS_OFF   (ES_OFF + ES_BYTES)
#define SMEM_BYTES (LS_OFF + 2 * BM * 4)        // 123904

__device__ float   g_gate[NK_];                      // gate * 1/sqrt(d)
__device__ float   g_inv_l[B_ * NQ_];
__device__ __half  g_Kh[(size_t)B_ * NK_ * D_];      // K * gate * scale, fp16
__device__ __half2 g_Vp[(size_t)B_ * (NK_/2) * D_];  // (V[2p][d], V[2p+1][d])

// ---------------------------------------------------------------------------
__global__ void gate_kernel(const float* __restrict__ phases) {
    int k = blockIdx.x * blockDim.x + threadIdx.x;
    if (k < NK_) {
        const float TWO_PI = 6.283185307179586f;
        const float INV_2PW2 = 1.0f / 1.2337005501361697f; // 2*(2pi/8)^2
        const float SCALE = 0.08838834764831845f;          // 1/sqrt(128)
        float p = fabsf(phases[k]);
        float pd = fminf(p, TWO_PI - p);
        g_gate[k] = expf(-pd * pd * INV_2PW2) * SCALE;
    }
}

// K -> fp16 with gate*scale folded. One thread per 4 elements.
__global__ void convK_kernel(const float* __restrict__ K) {
    int i = blockIdx.x * blockDim.x + threadIdx.x;   // < B*NK*D/4 = 2^20
    int d4  = (i & 31) << 2;
    int row = i >> 5;                                 // global (b*NK + n)
    float gs = g_gate[row & (NK_ - 1)];
    float4 v = *(const float4*)(K + (size_t)row * D_ + d4);
    __half2 h0 = __floats2half2_rn(v.x * gs, v.y * gs);
    __half2 h1 = __floats2half2_rn(v.z * gs, v.w * gs);
    uint2 u = make_uint2(*(uint32_t*)&h0, *(uint32_t*)&h1);
    *(uint2*)&g_Kh[(size_t)row * D_ + d4] = u;
}

// V -> fp16 k-pair packed: g_Vp[pr][d] = (V[2pr][d], V[2pr+1][d]).
__global__ void convV_kernel(const float* __restrict__ V) {
    int i = blockIdx.x * blockDim.x + threadIdx.x;   // < B*(NK/2)*D/4 = 2^19
    int d4 = (i & 31) << 2;
    int pr = i >> 5;                                  // global pair (b*NK/2 + p)
    const float* r0 = V + ((size_t)pr * 2 + 0) * D_ + d4;
    const float* r1 = V + ((size_t)pr * 2 + 1) * D_ + d4;
    float4 a = *(const float4*)r0;
    float4 b = *(const float4*)r1;
    __half2 h0 = __floats2half2_rn(a.x, b.x);
    __half2 h1 = __floats2half2_rn(a.y, b.y);
    __half2 h2 = __floats2half2_rn(a.z, b.z);
    __half2 h3 = __floats2half2_rn(a.w, b.w);
    uint4 u = make_uint4(*(uint32_t*)&h0, *(uint32_t*)&h1,
                         *(uint32_t*)&h2, *(uint32_t*)&h3);
    *(uint4*)&g_Vp[(size_t)pr * D_ + d4] = u;
}

// ---------------------------------------------------------------------------
__device__ __forceinline__ void mma_f16(
    float& d0, float& d1, float& d2, float& d3,
    uint32_t a0, uint32_t a1, uint32_t a2, uint32_t a3,
    uint32_t b0, uint32_t b1)
{
    asm volatile(
        "mma.sync.aligned.m16n8k16.row.col.f32.f16.f16.f32 "
        "{%0,%1,%2,%3}, {%4,%5,%6,%7}, {%8,%9}, {%0,%1,%2,%3};"
        : "+f"(d0), "+f"(d1), "+f"(d2), "+f"(d3)
        : "r"(a0), "r"(a1), "r"(a2), "r"(a3), "r"(b0), "r"(b1));
}

__device__ __forceinline__ void cp16(uint32_t dst, const void* src) {
    asm volatile("cp.async.ca.shared.global [%0], [%1], 16;"
                 :: "r"(dst), "l"(src));
}

// ---------------------------------------------------------------------------
// Fused attention, fp16-mma + cp.async double-buffered K/V.
// Single pass over K: E = exp(score) written UNNORMALIZED to attn; row-sum l
// and O = sum(E*v) accumulated in registers; O normalized at the end; attn
// fixed up by scale_attn_kernel. (No max subtraction: |score| <= ~6, exact.)
// ---------------------------------------------------------------------------
extern __shared__ char smem[];

__global__ void __launch_bounds__(NTHREADS, 1)
attn_kernel(const float* __restrict__ Q, float* __restrict__ out,
            float* __restrict__ attn)
{
    uint32_t sb = (uint32_t)__cvta_generic_to_shared(smem);
    uint32_t* Qsw = (uint32_t*)(smem + QS_OFF);
    float*    lsm = (float*)(smem + LS_OFF);

    const int b    = blockIdx.y;
    const int q0   = blockIdx.x * BM;
    const int brow = b * NQ_ + q0;

    const int tid  = threadIdx.x;
    const int lane = tid & 31;
    const int wid  = tid >> 5;
    const int g    = lane >> 2;        // 0..7
    const int t    = lane & 3;         // 0..3
    const int wm   = wid >> 1;         // 0..3 -> 32-row slab
    const int wn   = wid & 1;          // 0..1

    // ---- stage Q [BM][D] fp32 -> fp16 smem ----
    const float* Qg = Q + (size_t)brow * D_;
    for (int i = tid; i < BM * (D_ / 4); i += NTHREADS) {
        int m  = i >> 5;
        int d4 = (i & 31) << 2;
        float4 v = *(const float4*)(Qg + m * D_ + d4);
        __half2 h0 = __floats2half2_rn(v.x, v.y);
        __half2 h1 = __floats2half2_rn(v.z, v.w);
        uint2 u = make_uint2(*(uint32_t*)&h0, *(uint32_t*)&h1);
        *(uint2*)&Qsw[(m * QPH + d4) >> 1] = u;
    }

    // tile staging via cp.async (16B chunks; 8 per thread per tile)
    const __half*  KhB = g_Kh + (size_t)b * NK_ * D_;
    const __half2* VpB = g_Vp + (size_t)b * (NK_/2) * D_;
    auto stage = [&](int buf, int kt) {
        const int k0 = kt * BN;
        uint32_t kdst = sb + KS_OFF + buf * KS_BYTES;
        const __half* ksrc = KhB + (size_t)k0 * D_;
        #pragma unroll
        for (int r = 0; r < 4; r++) {
            int i = tid + r * NTHREADS;          // < 1024
            int row = i >> 4, off = i & 15;
            cp16(kdst + row * (KPH * 2) + off * 16, ksrc + row * D_ + off * 8);
        }
        uint32_t vdst = sb + VP_OFF + buf * VP_BYTES;
        const __half2* vsrc = VpB + (size_t)(k0 / 2) * D_;
        #pragma unroll
        for (int r = 0; r < 4; r++) {
            int i = tid + r * NTHREADS;          // < 1024
            int pr = i >> 5, off = i & 31;
            cp16(vdst + pr * (VPW * 4) + off * 16, vsrc + pr * D_ + off * 4);
        }
        asm volatile("cp.async.commit_group;");
    };

    stage(0, 0);

    float oacc[2][8][4];
    #pragma unroll
    for (int i = 0; i < 2; i++)
        #pragma unroll
        for (int j = 0; j < 8; j++)
            #pragma unroll
            for (int r = 0; r < 4; r++) oacc[i][j][r] = 0.0f;
    float lsum[2][2] = {{0.0f, 0.0f}, {0.0f, 0.0f}};

    const int arow = wm * 32 + g;
    uint32_t* Esw = (uint32_t*)(smem + ES_OFF);

    for (int kt = 0; kt < NT; ++kt) {
        const int cur = kt & 1;
        const int k0  = kt * BN;

        __syncthreads();                    // prev PV done with buf^1 & Es; Q staged (kt=0)
        if (kt + 1 < NT) {
            stage(cur ^ 1, kt + 1);
            asm volatile("cp.async.wait_group 1;");
        } else {
            asm volatile("cp.async.wait_group 0;");
        }
        __syncthreads();                    // tile kt visible to all threads

        const uint32_t* Ksw = (const uint32_t*)(smem + KS_OFF + cur * KS_BYTES);
        const uint32_t* Vpw = (const uint32_t*)(smem + VP_OFF + cur * VP_BYTES);

        // ---- S = Q K'^T : warp tile 32(m) x 32(n), k=128 in 8 k16 steps ----
        float sacc[2][4][4];
        #pragma unroll
        for (int i = 0; i < 2; i++)
            #pragma unroll
            for (int j = 0; j < 4; j++)
                #pragma unroll
                for (int r = 0; r < 4; r++) sacc[i][j][r] = 0.0f;

        const int bkey = wn * 32 + g;
        #pragma unroll
        for (int ks = 0; ks < 8; ++ks) {
            const int kw = ks * 8 + t;      // word within row
            uint32_t a[2][4];
            #pragma unroll
            for (int i = 0; i < 2; i++) {
                int r = arow + i * 16;
                a[i][0] = Qsw[(r * QPH >> 1) + kw];
                a[i][1] = Qsw[((r + 8) * QPH >> 1) + kw];
                a[i][2] = Qsw[(r * QPH >> 1) + kw + 4];
                a[i][3] = Qsw[((r + 8) * QPH >> 1) + kw + 4];
            }
            uint32_t bb[4][2];
            #pragma unroll
            for (int j = 0; j < 4; j++) {
                int key = bkey + j * 8;
                bb[j][0] = Ksw[(key * KPH >> 1) + kw];
                bb[j][1] = Ksw[(key * KPH >> 1) + kw + 4];
            }
            #pragma unroll
            for (int i = 0; i < 2; i++)
                #pragma unroll
                for (int j = 0; j < 4; j++)
                    mma_f16(sacc[i][j][0], sacc[i][j][1], sacc[i][j][2], sacc[i][j][3],
                            a[i][0], a[i][1], a[i][2], a[i][3],
                            bb[j][0], bb[j][1]);
        }

        // ---- epilogue: E = exp(S); attn gmem (fp32) + Es smem (fp16) ----
        #pragma unroll
        for (int i = 0; i < 2; i++) {
            const int rlo = wm * 32 + i * 16 + g;
            const int rhi = rlo + 8;
            #pragma unroll
            for (int j = 0; j < 4; j++) {
                const int cl = wn * 32 + j * 8 + 2 * t;
                float e0 = __expf(sacc[i][j][0]);
                float e1 = __expf(sacc[i][j][1]);
                float e2 = __expf(sacc[i][j][2]);
                float e3 = __expf(sacc[i][j][3]);
                lsum[i][0] += e0 + e1;
                lsum[i][1] += e2 + e3;
                *(float2*)(attn + (size_t)(brow + rlo) * NK_ + k0 + cl) = make_float2(e0, e1);
                *(float2*)(attn + (size_t)(brow + rhi) * NK_ + k0 + cl) = make_float2(e2, e3);
                __half2 hlo = __floats2half2_rn(e0, e1);
                __half2 hhi = __floats2half2_rn(e2, e3);
                Esw[(rlo * EPH + cl) >> 1] = *(uint32_t*)&hlo;
                Esw[(rhi * EPH + cl) >> 1] = *(uint32_t*)&hhi;
            }
        }
        __syncthreads();                    // Es visible

        // ---- O += E V : warp tile 32(m) x 64(n), k=64 in 4 k16 steps ----
        #pragma unroll
        for (int ks = 0; ks < 4; ++ks) {
            const int kw = ks * 8 + t;
            uint32_t a[2][4];
            #pragma unroll
            for (int i = 0; i < 2; i++) {
                int r = arow + i * 16;
                a[i][0] = Esw[(r * EPH >> 1) + kw];
                a[i][1] = Esw[((r + 8) * EPH >> 1) + kw];
                a[i][2] = Esw[(r * EPH >> 1) + kw + 4];
                a[i][3] = Esw[((r + 8) * EPH >> 1) + kw + 4];
            }
            #pragma unroll
            for (int j = 0; j < 8; j++) {
                const int dc = wn * 64 + j * 8 + g;
                uint32_t b0 = Vpw[(ks * 8 + t) * VPW + dc];
                uint32_t b1 = Vpw[(ks * 8 + t + 4) * VPW + dc];
                #pragma unroll
                for (int i = 0; i < 2; i++)
                    mma_f16(oacc[i][j][0], oacc[i][j][1], oacc[i][j][2], oacc[i][j][3],
                            a[i][0], a[i][1], a[i][2], a[i][3], b0, b1);
            }
        }
    }

    // ---- reduce lsum (4 lanes/group, then across the 2 n-warps) ----
    #pragma unroll
    for (int i = 0; i < 2; i++)
        #pragma unroll
        for (int h = 0; h < 2; h++) {
            float s = lsum[i][h];
            s += __shfl_xor_sync(0xffffffffu, s, 1);
            s += __shfl_xor_sync(0xffffffffu, s, 2);
            if (t == 0) lsm[wn * BM + wm * 32 + i * 16 + h * 8 + g] = s;
        }
    __syncthreads();
    if (tid < BM) {
        float inv = 1.0f / (lsm[tid] + lsm[BM + tid]);
        lsm[tid] = inv;
        g_inv_l[brow + tid] = inv;
    }
    __syncthreads();

    // ---- write normalized O ----
    #pragma unroll
    for (int i = 0; i < 2; i++) {
        const int rlo = wm * 32 + i * 16 + g;
        const int rhi = rlo + 8;
        const float invlo = lsm[rlo];
        const float invhi = lsm[rhi];
        #pragma unroll
        for (int j = 0; j < 8; j++) {
            const int col = wn * 64 + j * 8 + 2 * t;
            *(float2*)(out + (size_t)(brow + rlo) * D_ + col) =
                make_float2(oacc[i][j][0] * invlo, oacc[i][j][1] * invlo);
            *(float2*)(out + (size_t)(brow + rhi) * D_ + col) =
                make_float2(oacc[i][j][2] * invhi, oacc[i][j][3] * invhi);
        }
    }
}

// ---------------------------------------------------------------------------
// Normalize attention buffer: attn[row, :] *= 1/l[row]  (streaming, float4)
// ---------------------------------------------------------------------------
__global__ void scale_attn_kernel(float4* __restrict__ attn) {
    unsigned idx = blockIdx.x * blockDim.x + threadIdx.x;   // < 2^24
    unsigned row = idx >> 9;                                // / (NK_/4)
    float inv = g_inv_l[row];
    float4 v = attn[idx];
    v.x *= inv; v.y *= inv; v.z *= inv; v.w *= inv;
    attn[idx] = v;
}

// ---------------------------------------------------------------------------
extern "C" void kernel_launch(void* const* d_in, const int* in_sizes, int n_in,
                              void* d_out, int out_size) {
    const float* Q      = (const float*)d_in[0];
    const float* K      = (const float*)d_in[1];
    const float* V      = (const float*)d_in[2];
    const float* phases = (const float*)d_in[3];

    float* out  = (float*)d_out;
    float* attn = out + (size_t)B_ * NQ_ * D_;   // outputs: (output, attention)

    (void)in_sizes; (void)n_in; (void)out_size;

    cudaFuncSetAttribute(attn_kernel,
                         cudaFuncAttributeMaxDynamicSharedMemorySize, SMEM_BYTES);

    gate_kernel<<<(NK_ + 255) / 256, 256>>>(phases);
    convK_kernel<<<(B_ * NK_ * D_ / 4) / 256, 256>>>(K);
    convV_kernel<<<(B_ * (NK_/2) * D_ / 4) / 256, 256>>>(V);

    dim3 grid(NQ_ / BM, B_);
    attn_kernel<<<grid, NTHREADS, SMEM_BYTES>>>(Q, out, attn);

    scale_attn_kernel<<<65536, 256>>>((float4*)attn);
}